// round 2
// baseline (speedup 1.0000x reference)
#include <cuda_runtime.h>

// Problem constants
#define BB 4096   // batch
#define TT 512    // time steps
#define DD 8      // input dim
#define HH 64     // hidden
#define GG 256    // 4*H gates
#define TB 32     // batch tile per CTA
#define HS 68     // padded h row stride (conflict-free broadcast loads)
#define NT 128    // threads per CTA

// smem layout (floats):
//  wih0 [8][256] k-major   : 2048
//  whh0 [64][256] k-major  : 16384
//  wih1 [64][256] k-major  : 16384
//  whh1 [64][256] k-major  : 16384
//  b0, b1 (bih+bhh)        : 512
//  h0 [32][68], h1 [32][68]: 4352
//  x double buffer [2][32][8]: 512
#define SMEM_FLOATS (DD*GG + 3*HH*GG + 2*GG + 2*TB*HS + 2*TB*DD)
#define SMEM_BYTES  (SMEM_FLOATS * 4)

__device__ __forceinline__ float sigm(float z) {
    return 1.0f / (1.0f + __expf(-z));
}
__device__ __forceinline__ float tanh_f(float z) {
    return 2.0f / (1.0f + __expf(-2.0f * z)) - 1.0f;
}

#define FMA8(accp, hval, lo, hi)                                            \
    (accp)[0] += (hval)*(lo).x; (accp)[1] += (hval)*(lo).y;                 \
    (accp)[2] += (hval)*(lo).z; (accp)[3] += (hval)*(lo).w;                 \
    (accp)[4] += (hval)*(hi).x; (accp)[5] += (hval)*(hi).y;                 \
    (accp)[6] += (hval)*(hi).z; (accp)[7] += (hval)*(hi).w;

// acc[64]: acc[b*32 + gate_type*8 + u] for b in {0,1}, gate_type in {i,f,g,o}, u in 0..7
// hbuf: [TB][HS] row-major h state; wbuf: [64][256] k-major weights
__device__ __forceinline__ void gemm64(float* acc,
                                       const float* __restrict__ hbuf,
                                       const float* __restrict__ wbuf,
                                       int bA, int bB, int ug)
{
    #pragma unroll 2
    for (int k = 0; k < HH; k++) {
        float ha = hbuf[bA * HS + k];
        float hb = hbuf[bB * HS + k];
        const float4* wr = (const float4*)(wbuf + k * GG + ug * 8);
        #pragma unroll
        for (int g4 = 0; g4 < 4; g4++) {
            float4 lo = wr[g4 * 16];
            float4 hi = wr[g4 * 16 + 1];
            FMA8(acc + g4 * 8,      ha, lo, hi)
            FMA8(acc + 32 + g4 * 8, hb, lo, hi)
        }
    }
}

__device__ __forceinline__ void cell_update(const float* acc, float* c, float* nh)
{
    #pragma unroll
    for (int b = 0; b < 2; b++) {
        #pragma unroll
        for (int u = 0; u < 8; u++) {
            float iv = sigm(acc[b * 32 + 0 * 8 + u]);
            float fv = sigm(acc[b * 32 + 1 * 8 + u]);
            float gv = tanh_f(acc[b * 32 + 2 * 8 + u]);
            float ov = sigm(acc[b * 32 + 3 * 8 + u]);
            float cc = fv * c[b * 8 + u] + iv * gv;
            c[b * 8 + u]  = cc;
            nh[b * 8 + u] = ov * tanh_f(cc);
        }
    }
}

__global__ __launch_bounds__(NT, 1)
void lstm_fused(const float* __restrict__ x,
                const float* __restrict__ Wih0, const float* __restrict__ Whh0,
                const float* __restrict__ bih0, const float* __restrict__ bhh0,
                const float* __restrict__ Wih1, const float* __restrict__ Whh1,
                const float* __restrict__ bih1, const float* __restrict__ bhh1,
                const float* __restrict__ Wfc,  const float* __restrict__ bfc,
                float* __restrict__ out)
{
    extern __shared__ float sm[];
    float* s_wih0 = sm;                       // [8][256] k-major
    float* s_whh0 = s_wih0 + DD * GG;         // [64][256] k-major
    float* s_wih1 = s_whh0 + HH * GG;
    float* s_whh1 = s_wih1 + HH * GG;
    float* s_b0   = s_whh1 + HH * GG;         // [256]
    float* s_b1   = s_b0 + GG;
    float* s_h0   = s_b1 + GG;                // [32][68]
    float* s_h1   = s_h0 + TB * HS;
    float* s_x    = s_h1 + TB * HS;           // [2][32][8]

    const int tid = threadIdx.x;
    const int b0g = blockIdx.x * TB;

    // Weight load + transpose to k-major (coalesced gmem reads, one-time)
    for (int i = tid; i < GG * DD; i += NT) { int g = i >> 3, k = i & 7;  s_wih0[k * GG + g] = Wih0[i]; }
    for (int i = tid; i < GG * HH; i += NT) { int g = i >> 6, k = i & 63; s_whh0[k * GG + g] = Whh0[i]; }
    for (int i = tid; i < GG * HH; i += NT) { int g = i >> 6, k = i & 63; s_wih1[k * GG + g] = Wih1[i]; }
    for (int i = tid; i < GG * HH; i += NT) { int g = i >> 6, k = i & 63; s_whh1[k * GG + g] = Whh1[i]; }
    for (int i = tid; i < GG; i += NT) { s_b0[i] = bih0[i] + bhh0[i]; s_b1[i] = bih1[i] + bhh1[i]; }
    for (int i = tid; i < TB * HS; i += NT) { s_h0[i] = 0.f; s_h1[i] = 0.f; }
    // x for t = 0
    for (int i = tid; i < TB * DD; i += NT) {
        s_x[i] = x[(b0g + (i >> 3)) * (TT * DD) + (i & 7)];
    }
    __syncthreads();

    const int ug = tid & 7;        // unit group: units ug*8 .. ug*8+7
    const int bq = tid >> 3;       // batch pair index 0..15
    const int bA = bq * 2, bB = bA + 1;

    float c0[16], c1[16];
    #pragma unroll
    for (int i = 0; i < 16; i++) { c0[i] = 0.f; c1[i] = 0.f; }

    float acc[64];
    float nh[16];

    for (int t = 0; t < TT; t++) {
        const int cur = t & 1;

        // Prefetch x_{t+1} into registers (hidden under compute)
        float px0 = 0.f, px1 = 0.f;
        if (t + 1 < TT) {
            px0 = x[(b0g + (tid >> 3)) * (TT * DD) + (t + 1) * DD + (tid & 7)];
            px1 = x[(b0g + ((tid + NT) >> 3)) * (TT * DD) + (t + 1) * DD + (tid & 7)];
        }

        // ---------------- Layer 0 ----------------
        #pragma unroll
        for (int g4 = 0; g4 < 4; g4++) {
            #pragma unroll
            for (int u = 0; u < 8; u++) {
                float bv = s_b0[g4 * 64 + ug * 8 + u];
                acc[g4 * 8 + u]      = bv;
                acc[32 + g4 * 8 + u] = bv;
            }
        }
        // xg0 = x_t @ Wih0.T  (K = 8)
        {
            const float* xs = s_x + cur * (TB * DD);
            #pragma unroll
            for (int k = 0; k < DD; k++) {
                float ha = xs[bA * DD + k];
                float hb = xs[bB * DD + k];
                const float4* wr = (const float4*)(s_wih0 + k * GG + ug * 8);
                #pragma unroll
                for (int g4 = 0; g4 < 4; g4++) {
                    float4 lo = wr[g4 * 16];
                    float4 hi = wr[g4 * 16 + 1];
                    FMA8(acc + g4 * 8,      ha, lo, hi)
                    FMA8(acc + 32 + g4 * 8, hb, lo, hi)
                }
            }
        }
        // + h0_{t-1} @ Whh0.T
        gemm64(acc, s_h0, s_whh0, bA, bB, ug);
        cell_update(acc, c0, nh);

        __syncthreads();   // all gemm0 reads of s_h0 done
        #pragma unroll
        for (int b = 0; b < 2; b++) {
            #pragma unroll
            for (int u = 0; u < 8; u++)
                s_h0[(bA + b) * HS + ug * 8 + u] = nh[b * 8 + u];
        }
        if (t + 1 < TT) {
            s_x[(cur ^ 1) * (TB * DD) + tid]      = px0;
            s_x[(cur ^ 1) * (TB * DD) + tid + NT] = px1;
        }
        __syncthreads();   // s_h0 (= layer-1 input) ready

        // ---------------- Layer 1 ----------------
        #pragma unroll
        for (int g4 = 0; g4 < 4; g4++) {
            #pragma unroll
            for (int u = 0; u < 8; u++) {
                float bv = s_b1[g4 * 64 + ug * 8 + u];
                acc[g4 * 8 + u]      = bv;
                acc[32 + g4 * 8 + u] = bv;
            }
        }
        gemm64(acc, s_h0, s_wih1, bA, bB, ug);   // h1_t @ Wih1.T
        gemm64(acc, s_h1, s_whh1, bA, bB, ug);   // h2_{t-1} @ Whh1.T
        cell_update(acc, c1, nh);

        __syncthreads();   // all gemm1 reads of s_h1 done
        #pragma unroll
        for (int b = 0; b < 2; b++) {
            #pragma unroll
            for (int u = 0; u < 8; u++)
                s_h1[(bA + b) * HS + ug * 8 + u] = nh[b * 8 + u];
        }
        // next step's first read of s_h1 is after 2 more barriers; no extra sync needed
    }

    __syncthreads();
    // Final FC: out[b] = h2[b, T-1, :] . Wfc + bfc
    if (tid < TB) {
        float s = bfc[0];
        #pragma unroll
        for (int u = 0; u < HH; u++)
            s += s_h1[tid * HS + u] * Wfc[u];
        out[b0g + tid] = s;
    }
}

extern "C" void kernel_launch(void* const* d_in, const int* in_sizes, int n_in,
                              void* d_out, int out_size)
{
    (void)in_sizes; (void)n_in; (void)out_size;
    cudaFuncSetAttribute(lstm_fused, cudaFuncAttributeMaxDynamicSharedMemorySize, SMEM_BYTES);
    lstm_fused<<<BB / TB, NT, SMEM_BYTES>>>(
        (const float*)d_in[0],
        (const float*)d_in[1], (const float*)d_in[2],
        (const float*)d_in[3], (const float*)d_in[4],
        (const float*)d_in[5], (const float*)d_in[6],
        (const float*)d_in[7], (const float*)d_in[8],
        (const float*)d_in[9], (const float*)d_in[10],
        (float*)d_out);
}